// round 1
// baseline (speedup 1.0000x reference)
#include <cuda_runtime.h>
#include <cuda_fp16.h>

#define TC      16      // total channels
#define HID     128     // hidden
#define PCH     48      // perception channels = 3*TC
#define TILE    128     // pixels per block
#define THREADS 256
#define W1_STR  56      // half stride for Wh1 / As rows (conflict-free)
#define W2_STR  136     // half stride for Wh2 rows

// bytes of dynamic shared memory
// Gs: float[16*3*132] ; noise_s: float[128] ; b1s: float[128] ; b2s: float[16]
// Wh1: half[128*56] ; Wh2: half[16*136] ; As: half[128*56]
#define SMEM_BYTES ((16*3*132 + 128 + 128 + 16)*4 + (128*56 + 16*136 + 128*56)*2)

__device__ __forceinline__ void mma16816(float* d,
    unsigned a0, unsigned a1, unsigned a2, unsigned a3,
    unsigned b0, unsigned b1)
{
    asm volatile(
        "mma.sync.aligned.m16n8k16.row.col.f32.f16.f16.f32 "
        "{%0,%1,%2,%3}, {%4,%5,%6,%7}, {%8,%9}, {%0,%1,%2,%3};\n"
        : "+f"(d[0]), "+f"(d[1]), "+f"(d[2]), "+f"(d[3])
        : "r"(a0), "r"(a1), "r"(a2), "r"(a3), "r"(b0), "r"(b1));
}

__global__ __launch_bounds__(THREADS, 2)
void nca_step_kernel(const float* __restrict__ grid,
                     const float* __restrict__ noise,
                     const float* __restrict__ w1,
                     const float* __restrict__ b1,
                     const float* __restrict__ w2,
                     const float* __restrict__ b2,
                     float* __restrict__ out)
{
    extern __shared__ __align__(16) char smem_raw[];
    float* Gs      = (float*)smem_raw;            // [16][3][132]
    float* noise_s = Gs + 16*3*132;               // [128]
    float* b1s     = noise_s + 128;               // [128]
    float* b2s     = b1s + 128;                   // [16]
    half*  Wh1     = (half*)(b2s + 16);           // [128][56] (48 used)
    half*  Wh2     = Wh1 + 128*W1_STR;            // [16][136] (128 used)
    half*  As      = Wh2 + 16*W2_STR;             // [128][56] (48 used)

    const int tid = threadIdx.x;
    const int bid = blockIdx.x;
    const int b   = bid >> 9;          // 512 blocks per batch (256 rows * 2 tiles)
    const int rem = bid & 511;
    const int h   = rem >> 1;
    const int w0  = (rem & 1) << 7;

    // ---- stage weights / biases / noise ----
    for (int i = tid; i < HID*PCH; i += THREADS)
        Wh1[(i/PCH)*W1_STR + (i%PCH)] = __float2half(w1[i]);
    for (int i = tid; i < TC*HID; i += THREADS)
        Wh2[(i/HID)*W2_STR + (i%HID)] = __float2half(w2[i]);
    if (tid < HID) b1s[tid] = b1[tid];
    if (tid < TC)  b2s[tid] = b2[tid];
    if (tid < TILE) noise_s[tid] = noise[((b << 8) + h) * 256 + w0 + tid];

    // ---- stage grid tile (16 ch x 3 rows x 130 cols, zero halo) ----
    for (int i = tid; i < 16*3*130; i += THREADS) {
        int c   = i / 390;
        int r   = (i / 130) % 3;
        int col = i % 130;
        int hh  = h + r - 1;
        int ww  = w0 + col - 1;
        float v = 0.f;
        if (hh >= 0 && hh < 256 && ww >= 0 && ww < 256)
            v = grid[(((b*TC + c) << 8) + hh) * 256 + ww];
        Gs[(c*3 + r)*132 + col] = v;
    }
    __syncthreads();

    // ---- perception: identity / sobel_x / sobel_y (exact ref filters) ----
    for (int i = tid; i < TILE*TC; i += THREADS) {
        int pix = i & 127;
        int c   = i >> 7;
        const float* g0 = &Gs[(c*3)*132 + pix + 1];
        float tl = g0[-1],  tc_ = g0[0],   tr = g0[1];
        float ml = g0[131], mc  = g0[132], mr = g0[133];
        float bl = g0[263], bc  = g0[264], br = g0[265];
        // sobel_x as written in ref: [[1,0,1],[2,0,-2],[1,0,-1]]/8
        float sx = (tl + tr + 2.f*ml - 2.f*mr + bl - br) * 0.125f;
        float sy = (tl + 2.f*tc_ + tr - bl - 2.f*bc - br) * 0.125f;
        half* a = &As[pix*W1_STR + 3*c];
        a[0] = __float2half(mc);
        a[1] = __float2half(sx);
        a[2] = __float2half(sy);
    }
    __syncthreads();

    // ---- per-warp: 16 pixels, full MLP ----
    const int lane = tid & 31;
    const int g    = lane >> 2;
    const int tg   = lane & 3;
    const int m0   = (tid >> 5) << 4;

    float acc[16][4];
    #pragma unroll
    for (int nt = 0; nt < 16; nt++) {
        acc[nt][0] = 0.f; acc[nt][1] = 0.f; acc[nt][2] = 0.f; acc[nt][3] = 0.f;
    }

    const half* Arow0 = &As[(m0 + g    )*W1_STR + 2*tg];
    const half* Arow1 = &As[(m0 + g + 8)*W1_STR + 2*tg];

    // GEMM1: [128pix x 48] x w1^T[48 x 128]  (K = 48 -> 3 k-steps)
    #pragma unroll
    for (int kt = 0; kt < 3; kt++) {
        int k0 = kt << 4;
        unsigned a0 = *(const unsigned*)(Arow0 + k0);
        unsigned a1 = *(const unsigned*)(Arow1 + k0);
        unsigned a2 = *(const unsigned*)(Arow0 + k0 + 8);
        unsigned a3 = *(const unsigned*)(Arow1 + k0 + 8);
        #pragma unroll
        for (int nt = 0; nt < 16; nt++) {
            const half* bp = &Wh1[((nt << 3) + g)*W1_STR + k0 + 2*tg];
            unsigned b0r = *(const unsigned*)bp;
            unsigned b1r = *(const unsigned*)(bp + 8);
            mma16816(acc[nt], a0, a1, a2, a3, b0r, b1r);
        }
    }

    // bias + relu + pack into A-fragments for GEMM2 (C-frag layout == A-frag layout)
    unsigned hA[32];
    #pragma unroll
    for (int nt = 0; nt < 16; nt++) {
        float bb0 = b1s[(nt << 3) + 2*tg];
        float bb1 = b1s[(nt << 3) + 2*tg + 1];
        float h0 = fmaxf(acc[nt][0] + bb0, 0.f);
        float h1 = fmaxf(acc[nt][1] + bb1, 0.f);
        float h2 = fmaxf(acc[nt][2] + bb0, 0.f);
        float h3 = fmaxf(acc[nt][3] + bb1, 0.f);
        half2 p0 = __floats2half2_rn(h0, h1);   // low = even col
        half2 p1 = __floats2half2_rn(h2, h3);
        hA[2*nt    ] = *(unsigned*)&p0;
        hA[2*nt + 1] = *(unsigned*)&p1;
    }

    // GEMM2: [16pix x 128] x w2^T[128 x 16]  (K = 128 -> 8 k-steps, N = 16 -> 2 tiles)
    float acc2[2][4];
    #pragma unroll
    for (int nt = 0; nt < 2; nt++) {
        acc2[nt][0] = 0.f; acc2[nt][1] = 0.f; acc2[nt][2] = 0.f; acc2[nt][3] = 0.f;
    }
    #pragma unroll
    for (int kt = 0; kt < 8; kt++) {
        unsigned a0 = hA[4*kt + 0];
        unsigned a1 = hA[4*kt + 1];
        unsigned a2 = hA[4*kt + 2];
        unsigned a3 = hA[4*kt + 3];
        #pragma unroll
        for (int nt = 0; nt < 2; nt++) {
            const half* bp = &Wh2[((nt << 3) + g)*W2_STR + (kt << 4) + 2*tg];
            unsigned b0r = *(const unsigned*)bp;
            unsigned b1r = *(const unsigned*)(bp + 8);
            mma16816(acc2[nt], a0, a1, a2, a3, b0r, b1r);
        }
    }

    // ---- epilogue: +b2, stochastic mask, residual (fp32 grid), clip, store ----
    const int pix0 = m0 + g;
    const int pix1 = m0 + g + 8;
    const float mk0 = (noise_s[pix0] < 0.5f) ? 1.f : 0.f;
    const float mk1 = (noise_s[pix1] < 0.5f) ? 1.f : 0.f;
    const int out_base = ((b*TC) << 16) + (h << 8) + w0;   // + c*65536 + pix

    #pragma unroll
    for (int nt = 0; nt < 2; nt++) {
        #pragma unroll
        for (int rr = 0; rr < 2; rr++) {
            int   c     = (nt << 3) + 2*tg + rr;
            float bb    = b2s[c];
            float gc0   = Gs[(c*3 + 1)*132 + pix0 + 1];
            float gc1   = Gs[(c*3 + 1)*132 + pix1 + 1];
            float u0    = (acc2[nt][rr]     + bb) * mk0;
            float u1    = (acc2[nt][2 + rr] + bb) * mk1;
            float o0    = fminf(fmaxf(gc0 + u0, -2.f), 2.f);
            float o1    = fminf(fmaxf(gc1 + u1, -2.f), 2.f);
            out[out_base + (c << 16) + pix0] = o0;
            out[out_base + (c << 16) + pix1] = o1;
        }
    }
}

extern "C" void kernel_launch(void* const* d_in, const int* in_sizes, int n_in,
                              void* d_out, int out_size)
{
    const float* grid  = (const float*)d_in[0];
    const float* noise = (const float*)d_in[1];
    const float* w1    = (const float*)d_in[2];
    const float* b1    = (const float*)d_in[3];
    const float* w2    = (const float*)d_in[4];
    const float* b2    = (const float*)d_in[5];
    float* out = (float*)d_out;

    static bool attr_set = false;
    if (!attr_set) {
        cudaFuncSetAttribute(nca_step_kernel,
                             cudaFuncAttributeMaxDynamicSharedMemorySize,
                             SMEM_BYTES);
        attr_set = true;
    }

    const int nblocks = 32 * 256 * 2;   // B * H * (W / TILE)
    nca_step_kernel<<<nblocks, THREADS, SMEM_BYTES>>>(
        grid, noise, w1, b1, w2, b2, out);
}

// round 2
// speedup vs baseline: 1.2421x; 1.2421x over previous
#include <cuda_runtime.h>
#include <cuda_fp16.h>
#include <cstdint>

#define TC      16      // total channels
#define HID     128     // hidden
#define PCH     48      // perception channels = 3*TC
#define TILE    128     // pixels per block
#define THREADS 256
#define W1_STR  56      // half stride for Wh1 / As rows (conflict-free)
#define W2_STR  136     // half stride for Wh2 rows

// Gs: float[16*3*132] ; noise_s: float[128] ; b1s: float[128] ; b2s: float[16]
// Wh1: half[128*56] ; Wh2: half[16*136] ; As: half[128*56]
#define SMEM_BYTES ((16*3*132 + 128 + 128 + 16)*4 + (128*56 + 16*136 + 128*56)*2)

// Pre-converted half weights in fragment-ready padded layouts.
__device__ half g_wh1[HID * W1_STR];
__device__ half g_wh2[TC * W2_STR];

__global__ void convert_weights_kernel(const float* __restrict__ w1,
                                       const float* __restrict__ w2)
{
    int t = threadIdx.x;
    for (int i = t; i < HID * PCH; i += THREADS)
        g_wh1[(i / PCH) * W1_STR + (i % PCH)] = __float2half(w1[i]);
    for (int i = t; i < TC * HID; i += THREADS)
        g_wh2[(i / HID) * W2_STR + (i % HID)] = __float2half(w2[i]);
}

__device__ __forceinline__ void mma16816(float* d,
    unsigned a0, unsigned a1, unsigned a2, unsigned a3,
    unsigned b0, unsigned b1)
{
    asm volatile(
        "mma.sync.aligned.m16n8k16.row.col.f32.f16.f16.f32 "
        "{%0,%1,%2,%3}, {%4,%5,%6,%7}, {%8,%9}, {%0,%1,%2,%3};\n"
        : "+f"(d[0]), "+f"(d[1]), "+f"(d[2]), "+f"(d[3])
        : "r"(a0), "r"(a1), "r"(a2), "r"(a3), "r"(b0), "r"(b1));
}

__device__ __forceinline__ void ldm_x4(unsigned& r0, unsigned& r1,
                                       unsigned& r2, unsigned& r3,
                                       uint32_t addr)
{
    asm volatile(
        "ldmatrix.sync.aligned.m8n8.x4.shared.b16 {%0,%1,%2,%3}, [%4];\n"
        : "=r"(r0), "=r"(r1), "=r"(r2), "=r"(r3)
        : "r"(addr));
}

__global__ __launch_bounds__(THREADS, 2)
void nca_step_kernel(const float* __restrict__ grid,
                     const float* __restrict__ noise,
                     const float* __restrict__ b1,
                     const float* __restrict__ b2,
                     float* __restrict__ out)
{
    extern __shared__ __align__(16) char smem_raw[];
    float* Gs      = (float*)smem_raw;            // [16][3][132]
    float* noise_s = Gs + 16*3*132;               // [128]
    float* b1s     = noise_s + 128;               // [128]
    float* b2s     = b1s + 128;                   // [16]
    half*  Wh1     = (half*)(b2s + 16);           // [128][56] (48 used)
    half*  Wh2     = Wh1 + 128*W1_STR;            // [16][136] (128 used)
    half*  As      = Wh2 + 16*W2_STR;             // [128][56] (48 used)

    const int tid = threadIdx.x;
    const int bid = blockIdx.x;
    const int b   = bid >> 9;          // 512 blocks per batch (256 rows * 2 tiles)
    const int rem = bid & 511;
    const int h   = rem >> 1;
    const int w0  = (rem & 1) << 7;

    // ---- stage pre-converted half weights (vectorized) ----
    {
        const uint4* s1 = (const uint4*)g_wh1;
        uint4*       d1 = (uint4*)Wh1;
        #pragma unroll
        for (int i = tid; i < (HID*W1_STR)/8; i += THREADS) d1[i] = s1[i];
        const uint4* s2 = (const uint4*)g_wh2;
        uint4*       d2 = (uint4*)Wh2;
        #pragma unroll
        for (int i = tid; i < (TC*W2_STR)/8; i += THREADS) d2[i] = s2[i];
    }
    if (tid < HID)  b1s[tid] = b1[tid];
    if (tid < TC)   b2s[tid] = b2[tid];
    if (tid < TILE) noise_s[tid] = noise[((b << 8) + h) * 256 + w0 + tid];

    // ---- stage grid tile (16 ch x 3 rows x 130 cols, zero halo) ----
    for (int i = tid; i < 16*3*130; i += THREADS) {
        int c   = i / 390;
        int r   = (i / 130) % 3;
        int col = i % 130;
        int hh  = h + r - 1;
        int ww  = w0 + col - 1;
        float v = 0.f;
        if (hh >= 0 && hh < 256 && ww >= 0 && ww < 256)
            v = grid[(((b*TC + c) << 8) + hh) * 256 + ww];
        Gs[(c*3 + r)*132 + col] = v;
    }
    __syncthreads();

    // ---- perception: identity / sobel_x / sobel_y (exact ref filters) ----
    for (int i = tid; i < TILE*TC; i += THREADS) {
        int pix = i & 127;
        int c   = i >> 7;
        const float* g0 = &Gs[(c*3)*132 + pix + 1];
        float tl = g0[-1],  tc_ = g0[0],   tr = g0[1];
        float ml = g0[131], mc  = g0[132], mr = g0[133];
        float bl = g0[263], bc  = g0[264], br = g0[265];
        // sobel_x as written in ref: [[1,0,1],[2,0,-2],[1,0,-1]]/8
        float sx = (tl + tr + 2.f*ml - 2.f*mr + bl - br) * 0.125f;
        float sy = (tl + 2.f*tc_ + tr - bl - 2.f*bc - br) * 0.125f;
        half* a = &As[pix*W1_STR + 3*c];
        a[0] = __float2half(mc);
        a[1] = __float2half(sx);
        a[2] = __float2half(sy);
    }
    __syncthreads();

    // ---- per-warp: 16 pixels, full MLP ----
    const int lane = tid & 31;
    const int g    = lane >> 2;
    const int tg   = lane & 3;
    const int m0   = (tid >> 5) << 4;

    // ldmatrix per-lane base addresses (bytes, shared space)
    // A: lanes 0-15 -> rows m0+(lane&15), k-off 0; lanes 16-31 -> same rows, k-off 8
    const uint32_t a_base = (uint32_t)__cvta_generic_to_shared(As)
        + (uint32_t)(((m0 + (lane & 15)) * W1_STR + ((lane >> 4) << 3)) * 2);
    // B: lanes 0-7 n-rows 0-7 koff0 | 8-15 n-rows 0-7 koff8 | 16-23 n-rows 8-15 koff0 | 24-31 koff8
    const uint32_t brow = (lane & 7) + ((lane >> 4) << 3);
    const uint32_t bkof = (lane & 8);
    const uint32_t b1_base = (uint32_t)__cvta_generic_to_shared(Wh1)
        + (brow * W1_STR + bkof) * 2;
    const uint32_t b2_base = (uint32_t)__cvta_generic_to_shared(Wh2)
        + (brow * W2_STR + bkof) * 2;

    float acc[16][4];
    #pragma unroll
    for (int nt = 0; nt < 16; nt++) {
        acc[nt][0] = 0.f; acc[nt][1] = 0.f; acc[nt][2] = 0.f; acc[nt][3] = 0.f;
    }

    // GEMM1: [128pix x 48] x w1^T[48 x 128]  (K = 48 -> 3 k-steps)
    #pragma unroll
    for (int kt = 0; kt < 3; kt++) {
        unsigned a0, a1, a2, a3;
        ldm_x4(a0, a1, a2, a3, a_base + kt * 32);
        #pragma unroll
        for (int ntp = 0; ntp < 8; ntp++) {
            unsigned b0, b1r, b2r, b3;
            ldm_x4(b0, b1r, b2r, b3,
                   b1_base + (uint32_t)(ntp * 16 * W1_STR * 2) + kt * 32);
            mma16816(acc[2*ntp    ], a0, a1, a2, a3, b0,  b1r);
            mma16816(acc[2*ntp + 1], a0, a1, a2, a3, b2r, b3);
        }
    }

    // bias + relu + pack into A-fragments for GEMM2 (C-frag layout == A-frag layout)
    unsigned hA[32];
    #pragma unroll
    for (int nt = 0; nt < 16; nt++) {
        float bb0 = b1s[(nt << 3) + 2*tg];
        float bb1 = b1s[(nt << 3) + 2*tg + 1];
        float h0 = fmaxf(acc[nt][0] + bb0, 0.f);
        float h1 = fmaxf(acc[nt][1] + bb1, 0.f);
        float h2 = fmaxf(acc[nt][2] + bb0, 0.f);
        float h3 = fmaxf(acc[nt][3] + bb1, 0.f);
        half2 p0 = __floats2half2_rn(h0, h1);   // low = even col
        half2 p1 = __floats2half2_rn(h2, h3);
        hA[2*nt    ] = *(unsigned*)&p0;
        hA[2*nt + 1] = *(unsigned*)&p1;
    }

    // GEMM2: [16pix x 128] x w2^T[128 x 16]  (K = 128 -> 8 k-steps, N = 16 -> 2 tiles)
    float acc2[2][4];
    #pragma unroll
    for (int nt = 0; nt < 2; nt++) {
        acc2[nt][0] = 0.f; acc2[nt][1] = 0.f; acc2[nt][2] = 0.f; acc2[nt][3] = 0.f;
    }
    #pragma unroll
    for (int kt = 0; kt < 8; kt++) {
        unsigned b0, b1r, b2r, b3;
        ldm_x4(b0, b1r, b2r, b3, b2_base + kt * 32);
        mma16816(acc2[0], hA[4*kt], hA[4*kt+1], hA[4*kt+2], hA[4*kt+3], b0,  b1r);
        mma16816(acc2[1], hA[4*kt], hA[4*kt+1], hA[4*kt+2], hA[4*kt+3], b2r, b3);
    }

    // ---- epilogue: +b2, stochastic mask, residual (fp32 grid), clip, store ----
    const int pix0 = m0 + g;
    const int pix1 = m0 + g + 8;
    const float mk0 = (noise_s[pix0] < 0.5f) ? 1.f : 0.f;
    const float mk1 = (noise_s[pix1] < 0.5f) ? 1.f : 0.f;
    const int out_base = ((b*TC) << 16) + (h << 8) + w0;   // + c*65536 + pix

    #pragma unroll
    for (int nt = 0; nt < 2; nt++) {
        #pragma unroll
        for (int rr = 0; rr < 2; rr++) {
            int   c     = (nt << 3) + 2*tg + rr;
            float bb    = b2s[c];
            float gc0   = Gs[(c*3 + 1)*132 + pix0 + 1];
            float gc1   = Gs[(c*3 + 1)*132 + pix1 + 1];
            float u0    = (acc2[nt][rr]     + bb) * mk0;
            float u1    = (acc2[nt][2 + rr] + bb) * mk1;
            float o0    = fminf(fmaxf(gc0 + u0, -2.f), 2.f);
            float o1    = fminf(fmaxf(gc1 + u1, -2.f), 2.f);
            out[out_base + (c << 16) + pix0] = o0;
            out[out_base + (c << 16) + pix1] = o1;
        }
    }
}

extern "C" void kernel_launch(void* const* d_in, const int* in_sizes, int n_in,
                              void* d_out, int out_size)
{
    const float* grid  = (const float*)d_in[0];
    const float* noise = (const float*)d_in[1];
    const float* w1    = (const float*)d_in[2];
    const float* b1    = (const float*)d_in[3];
    const float* w2    = (const float*)d_in[4];
    const float* b2    = (const float*)d_in[5];
    float* out = (float*)d_out;

    static bool attr_set = false;
    if (!attr_set) {
        cudaFuncSetAttribute(nca_step_kernel,
                             cudaFuncAttributeMaxDynamicSharedMemorySize,
                             SMEM_BYTES);
        attr_set = true;
    }

    convert_weights_kernel<<<1, THREADS>>>(w1, w2);

    const int nblocks = 32 * 256 * 2;   // B * H * (W / TILE)
    nca_step_kernel<<<nblocks, THREADS, SMEM_BYTES>>>(
        grid, noise, b1, b2, out);
}

// round 3
// speedup vs baseline: 1.3719x; 1.1045x over previous
#include <cuda_runtime.h>
#include <cuda_fp16.h>
#include <cstdint>

#define TC      16
#define HID     128
#define PCH     48
#define TILE    128
#define THREADS 256
#define A_STR   56      // half stride for As rows (16B-aligned, conflict-free ldmatrix)

// Gs: float[16*3*136] ; As: half[128*56]
#define SMEM_BYTES (16*3*136*4 + 128*A_STR*2)

// Pre-converted weights (k-permuted w1: k = 16*filter + channel), half biases.
__device__ half  g_wh1[HID * PCH];     // [128][48] row-major, permuted k
__device__ half  g_wh2[TC * HID];      // [16][128] row-major
__device__ half2 g_b1h2[HID / 2];

__global__ void convert_weights_kernel(const float* __restrict__ w1,
                                       const float* __restrict__ b1,
                                       const float* __restrict__ w2)
{
    int t = threadIdx.x;
    for (int i = t; i < HID * PCH; i += THREADS) {
        int o = i / PCH, p = i % PCH;
        int c = p / 3, f = p % 3;                 // src col p = 3c+f
        g_wh1[o * PCH + f * 16 + c] = __float2half(w1[i]);
    }
    for (int i = t; i < TC * HID; i += THREADS)
        g_wh2[i] = __float2half(w2[i]);
    if (t < HID / 2)
        g_b1h2[t] = __floats2half2_rn(b1[2 * t], b1[2 * t + 1]);
}

__device__ __forceinline__ void mma_f16acc(unsigned* d,
    unsigned a0, unsigned a1, unsigned a2, unsigned a3,
    unsigned b0, unsigned b1)
{
    asm volatile(
        "mma.sync.aligned.m16n8k16.row.col.f16.f16.f16.f16 "
        "{%0,%1}, {%2,%3,%4,%5}, {%6,%7}, {%0,%1};\n"
        : "+r"(d[0]), "+r"(d[1])
        : "r"(a0), "r"(a1), "r"(a2), "r"(a3), "r"(b0), "r"(b1));
}

__device__ __forceinline__ void mma_f32acc(float* d,
    unsigned a0, unsigned a1, unsigned a2, unsigned a3,
    unsigned b0, unsigned b1)
{
    asm volatile(
        "mma.sync.aligned.m16n8k16.row.col.f32.f16.f16.f32 "
        "{%0,%1,%2,%3}, {%4,%5,%6,%7}, {%8,%9}, {%0,%1,%2,%3};\n"
        : "+f"(d[0]), "+f"(d[1]), "+f"(d[2]), "+f"(d[3])
        : "r"(a0), "r"(a1), "r"(a2), "r"(a3), "r"(b0), "r"(b1));
}

__device__ __forceinline__ void ldm_x4(unsigned& r0, unsigned& r1,
                                       unsigned& r2, unsigned& r3,
                                       uint32_t addr)
{
    asm volatile(
        "ldmatrix.sync.aligned.m8n8.x4.shared.b16 {%0,%1,%2,%3}, [%4];\n"
        : "=r"(r0), "=r"(r1), "=r"(r2), "=r"(r3)
        : "r"(addr));
}

__global__ __launch_bounds__(THREADS, 3)
void nca_step_kernel(const float* __restrict__ grid,
                     const float* __restrict__ noise,
                     const float* __restrict__ b2,
                     float* __restrict__ out)
{
    extern __shared__ __align__(16) char smem_raw[];
    float* Gs = (float*)smem_raw;                 // [16][3][136], interior at col 4
    half*  As = (half*)(Gs + 16*3*136);           // [128][56] (48 used)

    const int tid = threadIdx.x;
    const int bid = blockIdx.x;
    const int b   = bid >> 9;
    const int rem = bid & 511;
    const int h   = rem >> 1;
    const int w0  = (rem & 1) << 7;

    // ---- stage grid tile: interior vectorized float4, div-free ----
    #pragma unroll
    for (int j = 0; j < 6; j++) {
        int idx   = j * THREADS + tid;       // 0..1535
        int rowid = idx >> 5;                // 0..47
        int c     = rowid / 3;               // const-div -> mulhi
        int r     = rowid - c * 3;
        int colq  = idx & 31;
        int hh    = h + r - 1;
        float4 v  = make_float4(0.f, 0.f, 0.f, 0.f);
        if ((unsigned)hh < 256u)
            v = *(const float4*)&grid[((((b*TC + c) << 8) + hh) << 8) + w0 + (colq << 2)];
        *(float4*)&Gs[(c*3 + r)*136 + 4 + (colq << 2)] = v;
    }
    // halo: 48 rows x 2 side columns (Gs cols 3 and 132)
    if (tid < 96) {
        int rowid = tid >> 1;
        int side  = tid & 1;
        int c     = rowid / 3;
        int r     = rowid - c * 3;
        int hh    = h + r - 1;
        int ww    = side ? (w0 + 128) : (w0 - 1);
        float v   = 0.f;
        if ((unsigned)hh < 256u && (unsigned)ww < 256u)
            v = grid[((((b*TC + c) << 8) + hh) << 8) + ww];
        Gs[(c*3 + r)*136 + (side ? 132 : 3)] = v;
    }
    __syncthreads();

    // ---- perception (filter-major k): As[pix][f*16 + c] ----
    #pragma unroll
    for (int it = 0; it < 4; it++) {
        int idx = it * THREADS + tid;
        int pix = idx & 127;
        int cp  = idx >> 7;                  // channel pair 0..7
        float idv[2], sxv[2], syv[2];
        #pragma unroll
        for (int q = 0; q < 2; q++) {
            int c = 2*cp + q;
            const float* g0 = &Gs[(c*3)*136 + pix + 3];
            float tl = g0[0],   tc_ = g0[1],   tr = g0[2];
            float ml = g0[136], mc  = g0[137], mr = g0[138];
            float bl = g0[272], bc  = g0[273], br = g0[274];
            idv[q] = mc;
            // sobel_x exactly as in reference: [[1,0,1],[2,0,-2],[1,0,-1]]/8
            sxv[q] = (tl + tr + 2.f*ml - 2.f*mr + bl - br) * 0.125f;
            syv[q] = (tl + 2.f*tc_ + tr - bl - 2.f*bc - br) * 0.125f;
        }
        half* a = &As[pix*A_STR + 2*cp];
        *(half2*)(a)      = __floats2half2_rn(idv[0], idv[1]);
        *(half2*)(a + 16) = __floats2half2_rn(sxv[0], sxv[1]);
        *(half2*)(a + 32) = __floats2half2_rn(syv[0], syv[1]);
    }
    __syncthreads();

    // ---- per-warp MLP over 16 pixels ----
    const int lane = tid & 31;
    const int g    = lane >> 2;
    const int tg   = lane & 3;
    const int m0   = (tid >> 5) << 4;

    const uint32_t a_base = (uint32_t)__cvta_generic_to_shared(As)
        + (uint32_t)(((m0 + (lane & 15)) * A_STR + ((lane >> 4) << 3)) * 2);

    unsigned acc[16][2];
    #pragma unroll
    for (int nt = 0; nt < 16; nt++) { acc[nt][0] = 0u; acc[nt][1] = 0u; }

    // GEMM1: [128 x 48] x w1^T[48 x 128], fp16 accum, B frags via LDG (L1-hot)
    const half* W1p = g_wh1 + g * PCH + 2 * tg;
    #pragma unroll
    for (int kt = 0; kt < 3; kt++) {
        unsigned a0, a1, a2, a3;
        ldm_x4(a0, a1, a2, a3, a_base + kt * 32);
        #pragma unroll
        for (int nt = 0; nt < 16; nt++) {
            unsigned b0  = *(const unsigned*)(W1p + nt * (8*PCH) + kt * 16);
            unsigned b1r = *(const unsigned*)(W1p + nt * (8*PCH) + kt * 16 + 8);
            mma_f16acc(acc[nt], a0, a1, a2, a3, b0, b1r);
        }
    }

    // bias + relu (half2, in place) -> acc becomes GEMM2 A fragments
    {
        const half2* B1p = g_b1h2 + tg;
        const half2  z   = __float2half2_rn(0.f);
        #pragma unroll
        for (int nt = 0; nt < 16; nt++) {
            half2 bb = B1p[4 * nt];
            half2 v0 = __hmax2(__hadd2(*(half2*)&acc[nt][0], bb), z);
            half2 v1 = __hmax2(__hadd2(*(half2*)&acc[nt][1], bb), z);
            acc[nt][0] = *(unsigned*)&v0;
            acc[nt][1] = *(unsigned*)&v1;
        }
    }

    // GEMM2: [16 x 128] x w2^T[128 x 16], fp32 accum
    float acc2[2][4];
    #pragma unroll
    for (int nt = 0; nt < 2; nt++) {
        acc2[nt][0] = 0.f; acc2[nt][1] = 0.f; acc2[nt][2] = 0.f; acc2[nt][3] = 0.f;
    }
    const half* W2p = g_wh2 + g * HID + 2 * tg;
    #pragma unroll
    for (int kt = 0; kt < 8; kt++) {
        unsigned a0 = acc[2*kt][0],   a1 = acc[2*kt][1];
        unsigned a2 = acc[2*kt+1][0], a3 = acc[2*kt+1][1];
        #pragma unroll
        for (int nt = 0; nt < 2; nt++) {
            unsigned b0  = *(const unsigned*)(W2p + nt * (8*HID) + kt * 16);
            unsigned b1r = *(const unsigned*)(W2p + nt * (8*HID) + kt * 16 + 8);
            mma_f32acc(acc2[nt], a0, a1, a2, a3, b0, b1r);
        }
    }

    // ---- epilogue ----
    const int pix0 = m0 + g;
    const int pix1 = pix0 + 8;
    const float* nrow = noise + (((b << 8) + h) << 8) + w0;
    const float mk0 = (nrow[pix0] < 0.5f) ? 1.f : 0.f;
    const float mk1 = (nrow[pix1] < 0.5f) ? 1.f : 0.f;
    const int out_base = ((b*TC) << 16) + (h << 8) + w0;

    #pragma unroll
    for (int nt = 0; nt < 2; nt++) {
        #pragma unroll
        for (int rr = 0; rr < 2; rr++) {
            int   c   = (nt << 3) + 2*tg + rr;
            float bb  = b2[c];
            float gc0 = Gs[(c*3 + 1)*136 + pix0 + 4];
            float gc1 = Gs[(c*3 + 1)*136 + pix1 + 4];
            float u0  = (acc2[nt][rr]     + bb) * mk0;
            float u1  = (acc2[nt][2 + rr] + bb) * mk1;
            out[out_base + (c << 16) + pix0] = fminf(fmaxf(gc0 + u0, -2.f), 2.f);
            out[out_base + (c << 16) + pix1] = fminf(fmaxf(gc1 + u1, -2.f), 2.f);
        }
    }
}

extern "C" void kernel_launch(void* const* d_in, const int* in_sizes, int n_in,
                              void* d_out, int out_size)
{
    const float* grid  = (const float*)d_in[0];
    const float* noise = (const float*)d_in[1];
    const float* w1    = (const float*)d_in[2];
    const float* b1    = (const float*)d_in[3];
    const float* w2    = (const float*)d_in[4];
    const float* b2    = (const float*)d_in[5];
    float* out = (float*)d_out;

    static bool attr_set = false;
    if (!attr_set) {
        cudaFuncSetAttribute(nca_step_kernel,
                             cudaFuncAttributeMaxDynamicSharedMemorySize,
                             SMEM_BYTES);
        attr_set = true;
    }

    convert_weights_kernel<<<1, THREADS>>>(w1, b1, w2);

    const int nblocks = 32 * 256 * 2;   // B * H * (W / TILE)
    nca_step_kernel<<<nblocks, THREADS, SMEM_BYTES>>>(grid, noise, b2, out);
}

// round 4
// speedup vs baseline: 2.0972x; 1.5287x over previous
#include <cuda_runtime.h>
#include <cuda_fp16.h>
#include <cstdint>

#define TC      16
#define HID     128
#define PCH     48
#define TILE    128
#define THREADS 256
#define A_STR   56      // half stride for As / Wh1 rows (16B-aligned, ldmatrix conflict-free)
#define W2_STR  136     // half stride for Wh2 rows

// Gs: float[16*3*136] ; Wh1: half[128*56] ; Wh2: half[16*136] ; As: half[128*56]
#define SMEM_BYTES (16*3*136*4 + (128*A_STR + 16*W2_STR + 128*A_STR)*2)

// Pre-converted, pre-PADDED weights in fragment-ready layouts (k-permuted w1).
__device__ half  g_wh1p[HID * A_STR];    // [128][56], cols 0..47 = w1 with k = 16*f + c
__device__ half  g_wh2p[TC * W2_STR];    // [16][136], cols 0..127 = w2
__device__ half2 g_b1h2[HID / 2];

__global__ void convert_weights_kernel(const float* __restrict__ w1,
                                       const float* __restrict__ b1,
                                       const float* __restrict__ w2)
{
    int t = threadIdx.x;
    for (int i = t; i < HID * A_STR; i += THREADS) g_wh1p[i] = __float2half(0.f);
    for (int i = t; i < TC * W2_STR; i += THREADS) g_wh2p[i] = __float2half(0.f);
    __syncthreads();
    for (int i = t; i < HID * PCH; i += THREADS) {
        int o = i / PCH, p = i % PCH;
        int c = p / 3, f = p % 3;                 // src col p = 3c+f
        g_wh1p[o * A_STR + f * 16 + c] = __float2half(w1[i]);
    }
    for (int i = t; i < TC * HID; i += THREADS)
        g_wh2p[(i / HID) * W2_STR + (i % HID)] = __float2half(w2[i]);
    if (t < HID / 2)
        g_b1h2[t] = __floats2half2_rn(b1[2 * t], b1[2 * t + 1]);
}

__device__ __forceinline__ void mma_f16acc(unsigned* d,
    unsigned a0, unsigned a1, unsigned a2, unsigned a3,
    unsigned b0, unsigned b1)
{
    asm volatile(
        "mma.sync.aligned.m16n8k16.row.col.f16.f16.f16.f16 "
        "{%0,%1}, {%2,%3,%4,%5}, {%6,%7}, {%0,%1};\n"
        : "+r"(d[0]), "+r"(d[1])
        : "r"(a0), "r"(a1), "r"(a2), "r"(a3), "r"(b0), "r"(b1));
}

__device__ __forceinline__ void mma_f32acc(float* d,
    unsigned a0, unsigned a1, unsigned a2, unsigned a3,
    unsigned b0, unsigned b1)
{
    asm volatile(
        "mma.sync.aligned.m16n8k16.row.col.f32.f16.f16.f32 "
        "{%0,%1,%2,%3}, {%4,%5,%6,%7}, {%8,%9}, {%0,%1,%2,%3};\n"
        : "+f"(d[0]), "+f"(d[1]), "+f"(d[2]), "+f"(d[3])
        : "r"(a0), "r"(a1), "r"(a2), "r"(a3), "r"(b0), "r"(b1));
}

__device__ __forceinline__ void ldm_x4(unsigned& r0, unsigned& r1,
                                       unsigned& r2, unsigned& r3,
                                       uint32_t addr)
{
    asm volatile(
        "ldmatrix.sync.aligned.m8n8.x4.shared.b16 {%0,%1,%2,%3}, [%4];\n"
        : "=r"(r0), "=r"(r1), "=r"(r2), "=r"(r3)
        : "r"(addr));
}

__global__ __launch_bounds__(THREADS, 3)
void nca_step_kernel(const float* __restrict__ grid,
                     const float* __restrict__ noise,
                     const float* __restrict__ b2,
                     float* __restrict__ out)
{
    extern __shared__ __align__(16) char smem_raw[];
    float* Gs  = (float*)smem_raw;                 // [16][3][136], interior at col 4
    half*  Wh1 = (half*)(Gs + 16*3*136);           // [128][56]
    half*  Wh2 = Wh1 + HID * A_STR;                // [16][136]
    half*  As  = Wh2 + TC * W2_STR;                // [128][56]

    const int tid = threadIdx.x;
    const int bid = blockIdx.x;
    const int b   = bid >> 9;
    const int rem = bid & 511;
    const int h   = rem >> 1;
    const int w0  = (rem & 1) << 7;

    // ---- stage weights: pure vector memcpy (pre-padded layouts) ----
    {
        const uint4* s1 = (const uint4*)g_wh1p;
        uint4*       d1 = (uint4*)Wh1;
        #pragma unroll
        for (int i = tid; i < (HID*A_STR)/8; i += THREADS) d1[i] = s1[i];
        const uint4* s2 = (const uint4*)g_wh2p;
        uint4*       d2 = (uint4*)Wh2;
        #pragma unroll
        for (int i = tid; i < (TC*W2_STR)/8; i += THREADS) d2[i] = s2[i];
    }

    // ---- stage grid tile: interior vectorized float4, div-free ----
    #pragma unroll
    for (int j = 0; j < 6; j++) {
        int idx   = j * THREADS + tid;       // 0..1535
        int rowid = idx >> 5;                // 0..47
        int c     = rowid / 3;               // const-div -> mulhi
        int r     = rowid - c * 3;
        int colq  = idx & 31;
        int hh    = h + r - 1;
        float4 v  = make_float4(0.f, 0.f, 0.f, 0.f);
        if ((unsigned)hh < 256u)
            v = *(const float4*)&grid[((((b*TC + c) << 8) + hh) << 8) + w0 + (colq << 2)];
        *(float4*)&Gs[(c*3 + r)*136 + 4 + (colq << 2)] = v;
    }
    // halo: 48 rows x 2 side columns (Gs cols 3 and 132)
    if (tid < 96) {
        int rowid = tid >> 1;
        int side  = tid & 1;
        int c     = rowid / 3;
        int r     = rowid - c * 3;
        int hh    = h + r - 1;
        int ww    = side ? (w0 + 128) : (w0 - 1);
        float v   = 0.f;
        if ((unsigned)hh < 256u && (unsigned)ww < 256u)
            v = grid[((((b*TC + c) << 8) + hh) << 8) + ww];
        Gs[(c*3 + r)*136 + (side ? 132 : 3)] = v;
    }
    __syncthreads();

    // ---- perception (filter-major k): As[pix][f*16 + c] ----
    #pragma unroll
    for (int it = 0; it < 4; it++) {
        int idx = it * THREADS + tid;
        int pix = idx & 127;
        int cp  = idx >> 7;                  // channel pair 0..7
        float idv[2], sxv[2], syv[2];
        #pragma unroll
        for (int q = 0; q < 2; q++) {
            int c = 2*cp + q;
            const float* g0 = &Gs[(c*3)*136 + pix + 3];
            float tl = g0[0],   tc_ = g0[1],   tr = g0[2];
            float ml = g0[136], mc  = g0[137], mr = g0[138];
            float bl = g0[272], bc  = g0[273], br = g0[274];
            idv[q] = mc;
            // sobel_x exactly as in reference: [[1,0,1],[2,0,-2],[1,0,-1]]/8
            sxv[q] = (tl + tr + 2.f*ml - 2.f*mr + bl - br) * 0.125f;
            syv[q] = (tl + 2.f*tc_ + tr - bl - 2.f*bc - br) * 0.125f;
        }
        half* a = &As[pix*A_STR + 2*cp];
        *(half2*)(a)      = __floats2half2_rn(idv[0], idv[1]);
        *(half2*)(a + 16) = __floats2half2_rn(sxv[0], sxv[1]);
        *(half2*)(a + 32) = __floats2half2_rn(syv[0], syv[1]);
    }
    __syncthreads();

    // ---- per-warp MLP over 16 pixels ----
    const int lane = tid & 31;
    const int g    = lane >> 2;
    const int tg   = lane & 3;
    const int m0   = (tid >> 5) << 4;

    const uint32_t a_base = (uint32_t)__cvta_generic_to_shared(As)
        + (uint32_t)(((m0 + (lane & 15)) * A_STR + ((lane >> 4) << 3)) * 2);
    // B-fragment ldmatrix lane mapping (n-major pairs of 8x8 tiles, then k)
    const uint32_t brow = (lane & 7) + ((lane >> 4) << 3);
    const uint32_t bkof = (lane & 8);
    const uint32_t b1_base = (uint32_t)__cvta_generic_to_shared(Wh1)
        + (brow * A_STR + bkof) * 2;
    const uint32_t b2_base = (uint32_t)__cvta_generic_to_shared(Wh2)
        + (brow * W2_STR + bkof) * 2;

    unsigned acc[16][2];
    #pragma unroll
    for (int nt = 0; nt < 16; nt++) { acc[nt][0] = 0u; acc[nt][1] = 0u; }

    // GEMM1: [128 x 48] x w1^T[48 x 128], fp16 accum, B via ldmatrix
    #pragma unroll
    for (int kt = 0; kt < 3; kt++) {
        unsigned a0, a1, a2, a3;
        ldm_x4(a0, a1, a2, a3, a_base + kt * 32);
        #pragma unroll
        for (int ntp = 0; ntp < 8; ntp++) {
            unsigned b0, b1r, b2r, b3;
            ldm_x4(b0, b1r, b2r, b3,
                   b1_base + (uint32_t)(ntp * 16 * A_STR * 2) + kt * 32);
            mma_f16acc(acc[2*ntp    ], a0, a1, a2, a3, b0,  b1r);
            mma_f16acc(acc[2*ntp + 1], a0, a1, a2, a3, b2r, b3);
        }
    }

    // bias + relu (half2, in place) -> acc becomes GEMM2 A fragments
    {
        const half2* B1p = g_b1h2 + tg;
        const half2  z   = __float2half2_rn(0.f);
        #pragma unroll
        for (int nt = 0; nt < 16; nt++) {
            half2 bb = B1p[4 * nt];
            half2 v0 = __hmax2(__hadd2(*(half2*)&acc[nt][0], bb), z);
            half2 v1 = __hmax2(__hadd2(*(half2*)&acc[nt][1], bb), z);
            acc[nt][0] = *(unsigned*)&v0;
            acc[nt][1] = *(unsigned*)&v1;
        }
    }

    // GEMM2: [16 x 128] x w2^T[128 x 16], fp32 accum, B via ldmatrix
    float acc2[2][4];
    #pragma unroll
    for (int nt = 0; nt < 2; nt++) {
        acc2[nt][0] = 0.f; acc2[nt][1] = 0.f; acc2[nt][2] = 0.f; acc2[nt][3] = 0.f;
    }
    #pragma unroll
    for (int kt = 0; kt < 8; kt++) {
        unsigned b0, b1r, b2r, b3;
        ldm_x4(b0, b1r, b2r, b3, b2_base + kt * 32);
        unsigned a0 = acc[2*kt][0],   a1 = acc[2*kt][1];
        unsigned a2 = acc[2*kt+1][0], a3 = acc[2*kt+1][1];
        mma_f32acc(acc2[0], a0, a1, a2, a3, b0,  b1r);
        mma_f32acc(acc2[1], a0, a1, a2, a3, b2r, b3);
    }

    // ---- epilogue ----
    const int pix0 = m0 + g;
    const int pix1 = pix0 + 8;
    const float* nrow = noise + (((b << 8) + h) << 8) + w0;
    const float mk0 = (nrow[pix0] < 0.5f) ? 1.f : 0.f;
    const float mk1 = (nrow[pix1] < 0.5f) ? 1.f : 0.f;
    const int out_base = ((b*TC) << 16) + (h << 8) + w0;

    #pragma unroll
    for (int nt = 0; nt < 2; nt++) {
        #pragma unroll
        for (int rr = 0; rr < 2; rr++) {
            int   c   = (nt << 3) + 2*tg + rr;
            float bb  = b2[c];
            float gc0 = Gs[(c*3 + 1)*136 + pix0 + 4];
            float gc1 = Gs[(c*3 + 1)*136 + pix1 + 4];
            float u0  = (acc2[nt][rr]     + bb) * mk0;
            float u1  = (acc2[nt][2 + rr] + bb) * mk1;
            out[out_base + (c << 16) + pix0] = fminf(fmaxf(gc0 + u0, -2.f), 2.f);
            out[out_base + (c << 16) + pix1] = fminf(fmaxf(gc1 + u1, -2.f), 2.f);
        }
    }
}

extern "C" void kernel_launch(void* const* d_in, const int* in_sizes, int n_in,
                              void* d_out, int out_size)
{
    const float* grid  = (const float*)d_in[0];
    const float* noise = (const float*)d_in[1];
    const float* w1    = (const float*)d_in[2];
    const float* b1    = (const float*)d_in[3];
    const float* w2    = (const float*)d_in[4];
    const float* b2    = (const float*)d_in[5];
    float* out = (float*)d_out;

    static bool attr_set = false;
    if (!attr_set) {
        cudaFuncSetAttribute(nca_step_kernel,
                             cudaFuncAttributeMaxDynamicSharedMemorySize,
                             SMEM_BYTES);
        attr_set = true;
    }

    convert_weights_kernel<<<1, THREADS>>>(w1, b1, w2);

    const int nblocks = 32 * 256 * 2;   // B * H * (W / TILE)
    nca_step_kernel<<<nblocks, THREADS, SMEM_BYTES>>>(grid, noise, b2, out);
}

// round 7
// speedup vs baseline: 2.3497x; 1.1204x over previous
#include <cuda_runtime.h>
#include <cuda_fp16.h>
#include <cstdint>

#define TC      16
#define HID     128
#define PCH     48
#define THREADS 256
#define NTILES  16384

#define GS_STR  136                 // floats per Gs row, interior at col 4
#define AT_STR  136                 // halfs per AsT row (k-major A, transposed)
#define W1_STR  56
#define W2_STR  136

// smem: Gs float[16*3*136] | AsT half[48*136] | Wh1 half[128*56] | Wh2 half[16*136]
#define OFF_GS   0
#define OFF_AST  (16*3*GS_STR*4)                  // 26112
#define OFF_WH1  (OFF_AST + PCH*AT_STR*2)         // 39168
#define OFF_WH2  (OFF_WH1 + HID*W1_STR*2)         // 53504
#define SMEM_BYTES (OFF_WH2 + TC*W2_STR*2)        // 57856

// Pre-converted, pre-padded weights (k-permuted w1: k = 16*filter + channel).
__device__ __align__(16) half  g_wh1p[HID * W1_STR];
__device__ __align__(16) half  g_wh2p[TC * W2_STR];
__device__ __align__(16) half2 g_b1h2[HID / 2];

__global__ void convert_weights_kernel(const float* __restrict__ w1,
                                       const float* __restrict__ b1,
                                       const float* __restrict__ w2)
{
    int t = threadIdx.x;
    for (int i = t; i < HID * W1_STR; i += THREADS) g_wh1p[i] = __float2half(0.f);
    for (int i = t; i < TC * W2_STR; i += THREADS) g_wh2p[i] = __float2half(0.f);
    __syncthreads();
    for (int i = t; i < HID * PCH; i += THREADS) {
        int o = i / PCH, p = i % PCH;
        int c = p / 3, f = p % 3;                  // src col p = 3c+f
        g_wh1p[o * W1_STR + f * 16 + c] = __float2half(w1[i]);
    }
    for (int i = t; i < TC * HID; i += THREADS)
        g_wh2p[(i / HID) * W2_STR + (i % HID)] = __float2half(w2[i]);
    if (t < HID / 2)
        g_b1h2[t] = __floats2half2_rn(b1[2 * t], b1[2 * t + 1]);
}

__device__ __forceinline__ void mma_f16acc(unsigned* d,
    unsigned a0, unsigned a1, unsigned a2, unsigned a3,
    unsigned b0, unsigned b1)
{
    asm volatile(
        "mma.sync.aligned.m16n8k16.row.col.f16.f16.f16.f16 "
        "{%0,%1}, {%2,%3,%4,%5}, {%6,%7}, {%0,%1};\n"
        : "+r"(d[0]), "+r"(d[1])
        : "r"(a0), "r"(a1), "r"(a2), "r"(a3), "r"(b0), "r"(b1));
}

__device__ __forceinline__ void mma_f32acc(float* d,
    unsigned a0, unsigned a1, unsigned a2, unsigned a3,
    unsigned b0, unsigned b1)
{
    asm volatile(
        "mma.sync.aligned.m16n8k16.row.col.f32.f16.f16.f32 "
        "{%0,%1,%2,%3}, {%4,%5,%6,%7}, {%8,%9}, {%0,%1,%2,%3};\n"
        : "+f"(d[0]), "+f"(d[1]), "+f"(d[2]), "+f"(d[3])
        : "r"(a0), "r"(a1), "r"(a2), "r"(a3), "r"(b0), "r"(b1));
}

__device__ __forceinline__ void ldm_x4(unsigned& r0, unsigned& r1,
                                       unsigned& r2, unsigned& r3, uint32_t addr)
{
    asm volatile(
        "ldmatrix.sync.aligned.m8n8.x4.shared.b16 {%0,%1,%2,%3}, [%4];\n"
        : "=r"(r0), "=r"(r1), "=r"(r2), "=r"(r3) : "r"(addr));
}

__device__ __forceinline__ void ldm_x4_trans(unsigned& r0, unsigned& r1,
                                             unsigned& r2, unsigned& r3, uint32_t addr)
{
    asm volatile(
        "ldmatrix.sync.aligned.m8n8.x4.trans.shared.b16 {%0,%1,%2,%3}, [%4];\n"
        : "=r"(r0), "=r"(r1), "=r"(r2), "=r"(r3) : "r"(addr));
}

__global__ __launch_bounds__(THREADS, 3)
void nca_step_kernel(const float* __restrict__ grid,
                     const float* __restrict__ noise,
                     const float* __restrict__ b2,
                     float* __restrict__ out,
                     int ncta)
{
    extern __shared__ __align__(128) char smem_raw[];
    float* Gs  = (float*)(smem_raw + OFF_GS);      // [16][3][136], interior at col 4
    half*  AsT = (half*)(smem_raw + OFF_AST);      // [48][136] k-major
    half*  Wh1 = (half*)(smem_raw + OFF_WH1);      // [128][56]
    half*  Wh2 = (half*)(smem_raw + OFF_WH2);      // [16][136]

    const int tid = threadIdx.x;
    const int cta = blockIdx.x;
    const int niter = (NTILES - cta + ncta - 1) / ncta;

    // ---- stage weights once per CTA (vector memcpy of pre-padded layouts) ----
    {
        const uint4* s1 = (const uint4*)g_wh1p;
        uint4*       d1 = (uint4*)Wh1;
        for (int i = tid; i < (HID*W1_STR)/8; i += THREADS) d1[i] = s1[i];
        const uint4* s2 = (const uint4*)g_wh2p;
        uint4*       d2 = (uint4*)Wh2;
        for (int i = tid; i < (TC*W2_STR)/8; i += THREADS) d2[i] = s2[i];
    }

    // ---- per-thread constants ----
    const int lane = tid & 31;
    const int g    = lane >> 2;
    const int tg   = lane & 3;
    const int m0   = (tid >> 5) << 4;

    // A (trans) ldmatrix base: lane -> AsT row (lane&7)+((lane>>4)<<3), col m0+(lane&8)
    const uint32_t a_base = (uint32_t)__cvta_generic_to_shared(AsT)
        + (uint32_t)(((((lane & 7) + ((lane >> 4) << 3)) * AT_STR) + m0 + (lane & 8)) * 2);
    // B ldmatrix bases (n-major 8x8 tile pairs, then k) — identical to R4 (verified)
    const uint32_t brow = (lane & 7) + ((lane >> 4) << 3);
    const uint32_t bkof = (lane & 8);
    const uint32_t b1_base = (uint32_t)__cvta_generic_to_shared(Wh1) + (brow * W1_STR + bkof) * 2;
    const uint32_t b2_base = (uint32_t)__cvta_generic_to_shared(Wh2) + (brow * W2_STR + bkof) * 2;

    __syncthreads();

    for (int i = 0; i < niter; i++) {
        const int tile = cta + i * ncta;
        const int b    = tile >> 9;
        const int h    = (tile >> 1) & 255;
        const int w0   = (tile & 1) << 7;

        // ---- stage grid tile: interior vectorized float4, div-free (R4-verified) ----
        #pragma unroll
        for (int j = 0; j < 6; j++) {
            int idx   = j * THREADS + tid;       // 0..1535
            int rowid = idx >> 5;                // 0..47
            int c     = rowid / 3;
            int r     = rowid - c * 3;
            int colq  = idx & 31;
            int hh    = h + r - 1;
            float4 v  = make_float4(0.f, 0.f, 0.f, 0.f);
            if ((unsigned)hh < 256u)
                v = *(const float4*)&grid[((((b*TC + c) << 8) + hh) << 8) + w0 + (colq << 2)];
            *(float4*)&Gs[(c*3 + r)*GS_STR + 4 + (colq << 2)] = v;
        }
        // halo: 48 rows x 2 side columns (Gs cols 3 and 132)
        if (tid < 96) {
            int rowid = tid >> 1;
            int side  = tid & 1;
            int c     = rowid / 3;
            int r     = rowid - c * 3;
            int hh    = h + r - 1;
            int ww    = side ? (w0 + 128) : (w0 - 1);
            float v   = 0.f;
            if ((unsigned)hh < 256u && (unsigned)ww < 256u)
                v = grid[((((b*TC + c) << 8) + hh) << 8) + ww];
            Gs[(c*3 + r)*GS_STR + (side ? 132 : 3)] = v;
        }
        __syncthreads();

        // ---- perception -> AsT[k][pix] (k = filter*16 + channel), conflict-free ----
        #pragma unroll
        for (int it = 0; it < 4; it++) {
            int idx = it * THREADS + tid;
            int pix = idx & 127;
            int cp  = idx >> 7;                  // channel pair 0..7
            #pragma unroll
            for (int q = 0; q < 2; q++) {
                int c = 2*cp + q;
                const float* g0 = &Gs[(c*3)*GS_STR + pix + 3];
                float tl = g0[0],        tc_ = g0[1],          tr = g0[2];
                float ml = g0[GS_STR],   mc  = g0[GS_STR+1],   mr = g0[GS_STR+2];
                float bl = g0[2*GS_STR], bc  = g0[2*GS_STR+1], br = g0[2*GS_STR+2];
                // sobel_x exactly as in reference: [[1,0,1],[2,0,-2],[1,0,-1]]/8
                float sx = (tl + tr + 2.f*ml - 2.f*mr + bl - br) * 0.125f;
                float sy = (tl + 2.f*tc_ + tr - bl - 2.f*bc - br) * 0.125f;
                AsT[c        *AT_STR + pix] = __float2half(mc);
                AsT[(16 + c) *AT_STR + pix] = __float2half(sx);
                AsT[(32 + c) *AT_STR + pix] = __float2half(sy);
            }
        }
        __syncthreads();

        // ---- GEMM1: [128 x 48] x w1^T[48 x 128], fp16 accum ----
        unsigned acc[16][2];
        #pragma unroll
        for (int nt = 0; nt < 16; nt++) { acc[nt][0] = 0u; acc[nt][1] = 0u; }

        #pragma unroll
        for (int kt = 0; kt < 3; kt++) {
            unsigned a0, a1, a2, a3;
            ldm_x4_trans(a0, a1, a2, a3, a_base + kt * (16 * AT_STR * 2));
            #pragma unroll
            for (int ntp = 0; ntp < 8; ntp++) {
                unsigned b0, b1r, b2r, b3;
                ldm_x4(b0, b1r, b2r, b3,
                       b1_base + (uint32_t)(ntp * 16 * W1_STR * 2) + kt * 32);
                mma_f16acc(acc[2*ntp    ], a0, a1, a2, a3, b0,  b1r);
                mma_f16acc(acc[2*ntp + 1], a0, a1, a2, a3, b2r, b3);
            }
        }

        // bias + relu (half2, in place) -> acc becomes GEMM2 A fragments
        {
            const half2* B1p = g_b1h2 + tg;
            const half2  z   = __float2half2_rn(0.f);
            #pragma unroll
            for (int nt = 0; nt < 16; nt++) {
                half2 bb = B1p[4 * nt];
                half2 v0 = __hmax2(__hadd2(*(half2*)&acc[nt][0], bb), z);
                half2 v1 = __hmax2(__hadd2(*(half2*)&acc[nt][1], bb), z);
                acc[nt][0] = *(unsigned*)&v0;
                acc[nt][1] = *(unsigned*)&v1;
            }
        }

        // ---- GEMM2: [16 x 128] x w2^T[128 x 16], fp32 accum ----
        float acc2[2][4];
        #pragma unroll
        for (int nt = 0; nt < 2; nt++) {
            acc2[nt][0] = 0.f; acc2[nt][1] = 0.f; acc2[nt][2] = 0.f; acc2[nt][3] = 0.f;
        }
        #pragma unroll
        for (int kt = 0; kt < 8; kt++) {
            unsigned b0, b1r, b2r, b3;
            ldm_x4(b0, b1r, b2r, b3, b2_base + kt * 32);
            unsigned a0 = acc[2*kt][0],   a1 = acc[2*kt][1];
            unsigned a2 = acc[2*kt+1][0], a3 = acc[2*kt+1][1];
            mma_f32acc(acc2[0], a0, a1, a2, a3, b0,  b1r);
            mma_f32acc(acc2[1], a0, a1, a2, a3, b2r, b3);
        }

        // ---- epilogue ----
        const int pix0 = m0 + g;
        const int pix1 = pix0 + 8;
        const float* nrow = noise + (((b << 8) + h) << 8) + w0;
        const float mk0 = (nrow[pix0] < 0.5f) ? 1.f : 0.f;
        const float mk1 = (nrow[pix1] < 0.5f) ? 1.f : 0.f;
        const int out_base = ((b*TC) << 16) + (h << 8) + w0;

        #pragma unroll
        for (int nt = 0; nt < 2; nt++) {
            #pragma unroll
            for (int rr = 0; rr < 2; rr++) {
                int   c   = (nt << 3) + 2*tg + rr;
                float bb  = b2[c];
                float gc0 = Gs[(c*3 + 1)*GS_STR + pix0 + 4];
                float gc1 = Gs[(c*3 + 1)*GS_STR + pix1 + 4];
                float u0  = (acc2[nt][rr]     + bb) * mk0;
                float u1  = (acc2[nt][2 + rr] + bb) * mk1;
                out[out_base + (c << 16) + pix0] = fminf(fmaxf(gc0 + u0, -2.f), 2.f);
                out[out_base + (c << 16) + pix1] = fminf(fmaxf(gc1 + u1, -2.f), 2.f);
            }
        }
        __syncthreads();
    }
}

extern "C" void kernel_launch(void* const* d_in, const int* in_sizes, int n_in,
                              void* d_out, int out_size)
{
    const float* grid  = (const float*)d_in[0];
    const float* noise = (const float*)d_in[1];
    const float* w1    = (const float*)d_in[2];
    const float* b1    = (const float*)d_in[3];
    const float* w2    = (const float*)d_in[4];
    const float* b2    = (const float*)d_in[5];
    float* out = (float*)d_out;

    static bool attr_set = false;
    if (!attr_set) {
        cudaFuncSetAttribute(nca_step_kernel,
                             cudaFuncAttributeMaxDynamicSharedMemorySize, SMEM_BYTES);
        attr_set = true;
    }

    int nsm = 148;
    cudaDeviceGetAttribute(&nsm, cudaDevAttrMultiProcessorCount, 0);
    int ncta = nsm * 3;
    if (ncta > NTILES) ncta = NTILES;

    convert_weights_kernel<<<1, THREADS>>>(w1, b1, w2);
    nca_step_kernel<<<ncta, THREADS, SMEM_BYTES>>>(grid, noise, b2, out, ncta);
}

// round 8
// speedup vs baseline: 2.6750x; 1.1385x over previous
#include <cuda_runtime.h>
#include <cuda_fp16.h>
#include <cstdint>

#define TC      16
#define HID     128
#define PCH     48
#define THREADS 256
#define NROWT   8192                // row-tiles: 32 batches * 256 rows

#define GS_STR  264                 // floats per Gs row, interior at col 4 (pix 0..255)
#define AT_STR  264                 // halfs per AsT row
#define W1_STR  56
#define W2_STR  136

// smem: Gs float[16*3*264] | AsT half[48*264] | Wh1 half[128*56] | Wh2 half[16*136]
#define OFF_GS   0
#define OFF_AST  (16*3*GS_STR*4)                  // 50688
#define OFF_WH1  (OFF_AST + PCH*AT_STR*2)         // 76032
#define OFF_WH2  (OFF_WH1 + HID*W1_STR*2)         // 90368
#define SMEM_BYTES (OFF_WH2 + TC*W2_STR*2)        // 94720

// Pre-converted, pre-padded weights (k-permuted w1: k = 16*filter + channel).
__device__ __align__(16) half  g_wh1p[HID * W1_STR];
__device__ __align__(16) half  g_wh2p[TC * W2_STR];
__device__ __align__(16) half2 g_b1h2[HID / 2];

__global__ void convert_weights_kernel(const float* __restrict__ w1,
                                       const float* __restrict__ b1,
                                       const float* __restrict__ w2)
{
    int t = threadIdx.x;
    for (int i = t; i < HID * W1_STR; i += THREADS) g_wh1p[i] = __float2half(0.f);
    for (int i = t; i < TC * W2_STR; i += THREADS) g_wh2p[i] = __float2half(0.f);
    __syncthreads();
    for (int i = t; i < HID * PCH; i += THREADS) {
        int o = i / PCH, p = i % PCH;
        int c = p / 3, f = p % 3;                  // src col p = 3c+f
        g_wh1p[o * W1_STR + f * 16 + c] = __float2half(w1[i]);
    }
    for (int i = t; i < TC * HID; i += THREADS)
        g_wh2p[(i / HID) * W2_STR + (i % HID)] = __float2half(w2[i]);
    if (t < HID / 2)
        g_b1h2[t] = __floats2half2_rn(b1[2 * t], b1[2 * t + 1]);
}

__device__ __forceinline__ void mma_f16acc(unsigned* d,
    unsigned a0, unsigned a1, unsigned a2, unsigned a3,
    unsigned b0, unsigned b1)
{
    asm volatile(
        "mma.sync.aligned.m16n8k16.row.col.f16.f16.f16.f16 "
        "{%0,%1}, {%2,%3,%4,%5}, {%6,%7}, {%0,%1};\n"
        : "+r"(d[0]), "+r"(d[1])
        : "r"(a0), "r"(a1), "r"(a2), "r"(a3), "r"(b0), "r"(b1));
}

__device__ __forceinline__ void mma_f32acc(float* d,
    unsigned a0, unsigned a1, unsigned a2, unsigned a3,
    unsigned b0, unsigned b1)
{
    asm volatile(
        "mma.sync.aligned.m16n8k16.row.col.f32.f16.f16.f32 "
        "{%0,%1,%2,%3}, {%4,%5,%6,%7}, {%8,%9}, {%0,%1,%2,%3};\n"
        : "+f"(d[0]), "+f"(d[1]), "+f"(d[2]), "+f"(d[3])
        : "r"(a0), "r"(a1), "r"(a2), "r"(a3), "r"(b0), "r"(b1));
}

__device__ __forceinline__ void ldm_x4(unsigned& r0, unsigned& r1,
                                       unsigned& r2, unsigned& r3, uint32_t addr)
{
    asm volatile(
        "ldmatrix.sync.aligned.m8n8.x4.shared.b16 {%0,%1,%2,%3}, [%4];\n"
        : "=r"(r0), "=r"(r1), "=r"(r2), "=r"(r3) : "r"(addr));
}

__device__ __forceinline__ void ldm_x4_trans(unsigned& r0, unsigned& r1,
                                             unsigned& r2, unsigned& r3, uint32_t addr)
{
    asm volatile(
        "ldmatrix.sync.aligned.m8n8.x4.trans.shared.b16 {%0,%1,%2,%3}, [%4];\n"
        : "=r"(r0), "=r"(r1), "=r"(r2), "=r"(r3) : "r"(addr));
}

__global__ __launch_bounds__(THREADS, 2)
void nca_step_kernel(const float* __restrict__ grid,
                     const float* __restrict__ noise,
                     const float* __restrict__ b2,
                     float* __restrict__ out,
                     int ncta)
{
    extern __shared__ __align__(128) char smem_raw[];
    float* Gs  = (float*)(smem_raw + OFF_GS);      // [16][3][264], interior at col 4
    half*  AsT = (half*)(smem_raw + OFF_AST);      // [48][264] k-major
    half*  Wh1 = (half*)(smem_raw + OFF_WH1);      // [128][56]
    half*  Wh2 = (half*)(smem_raw + OFF_WH2);      // [16][136]

    const int tid = threadIdx.x;
    const int cta = blockIdx.x;
    const int niter = (NROWT - cta + ncta - 1) / ncta;

    // ---- stage weights once per CTA (vector memcpy of pre-padded layouts) ----
    {
        const uint4* s1 = (const uint4*)g_wh1p;
        uint4*       d1 = (uint4*)Wh1;
        for (int i = tid; i < (HID*W1_STR)/8; i += THREADS) d1[i] = s1[i];
        const uint4* s2 = (const uint4*)g_wh2p;
        uint4*       d2 = (uint4*)Wh2;
        for (int i = tid; i < (TC*W2_STR)/8; i += THREADS) d2[i] = s2[i];
    }

    // ---- per-thread constants ----
    const int lane = tid & 31;
    const int g    = lane >> 2;
    const int tg   = lane & 3;
    const int m0   = (tid >> 5) << 5;              // 32 pixels per warp

    // A (trans) ldmatrix bases for the two 16-px sub-tiles
    const uint32_t ast_sm = (uint32_t)__cvta_generic_to_shared(AsT);
    const uint32_t a_row  = (lane & 7) + ((lane >> 4) << 3);
    const uint32_t a_b0   = ast_sm + (uint32_t)((a_row * AT_STR + m0      + (lane & 8)) * 2);
    const uint32_t a_b1   = ast_sm + (uint32_t)((a_row * AT_STR + m0 + 16 + (lane & 8)) * 2);
    // B ldmatrix bases (n-major 8x8 tile pairs, then k)
    const uint32_t brow = (lane & 7) + ((lane >> 4) << 3);
    const uint32_t bkof = (lane & 8);
    const uint32_t b1_base = (uint32_t)__cvta_generic_to_shared(Wh1) + (brow * W1_STR + bkof) * 2;
    const uint32_t b2_base = (uint32_t)__cvta_generic_to_shared(Wh2) + (brow * W2_STR + bkof) * 2;

    __syncthreads();

    for (int i = 0; i < niter; i++) {
        const int tile = cta + i * ncta;           // row-tile: b*256 + h
        const int b    = tile >> 8;
        const int h    = tile & 255;

        // ---- stage grid row-tile: 48 rows x 64 float4 interior ----
        #pragma unroll
        for (int j = 0; j < 12; j++) {
            int idx   = j * THREADS + tid;       // 0..3071
            int rowid = idx >> 6;                // 0..47
            int c     = rowid / 3;
            int r     = rowid - c * 3;
            int colq  = idx & 63;
            int hh    = h + r - 1;
            float4 v  = make_float4(0.f, 0.f, 0.f, 0.f);
            if ((unsigned)hh < 256u)
                v = *(const float4*)&grid[((((b*TC + c) << 8) + hh) << 8) + (colq << 2)];
            *(float4*)&Gs[(c*3 + r)*GS_STR + 4 + (colq << 2)] = v;
        }
        // halo: 48 rows x 2 side columns (Gs cols 3 and 260) — both OOB -> 0
        if (tid < 96) {
            int rowid = tid >> 1;
            int side  = tid & 1;
            int c     = rowid / 3;
            int r     = rowid - c * 3;
            Gs[(c*3 + r)*GS_STR + (side ? 260 : 3)] = 0.f;
        }
        __syncthreads();

        // ---- perception -> AsT[k][pix] (k = filter*16 + channel) ----
        #pragma unroll
        for (int it = 0; it < 8; it++) {
            int idx = it * THREADS + tid;
            int pix = idx & 255;
            int cp  = idx >> 8;                  // channel pair 0..7
            #pragma unroll
            for (int q = 0; q < 2; q++) {
                int c = 2*cp + q;
                const float* g0 = &Gs[(c*3)*GS_STR + pix + 3];
                float tl = g0[0],        tc_ = g0[1],          tr = g0[2];
                float ml = g0[GS_STR],   mc  = g0[GS_STR+1],   mr = g0[GS_STR+2];
                float bl = g0[2*GS_STR], bc  = g0[2*GS_STR+1], br = g0[2*GS_STR+2];
                // sobel_x exactly as in reference: [[1,0,1],[2,0,-2],[1,0,-1]]/8
                float sx = (tl + tr + 2.f*ml - 2.f*mr + bl - br) * 0.125f;
                float sy = (tl + 2.f*tc_ + tr - bl - 2.f*bc - br) * 0.125f;
                AsT[c        *AT_STR + pix] = __float2half(mc);
                AsT[(16 + c) *AT_STR + pix] = __float2half(sx);
                AsT[(32 + c) *AT_STR + pix] = __float2half(sy);
            }
        }
        __syncthreads();

        // ---- GEMM1: [256 x 48] x w1^T[48 x 128], fp16 accum, 2 sub-tiles/warp ----
        unsigned acc[2][16][2];
        #pragma unroll
        for (int s = 0; s < 2; s++)
            #pragma unroll
            for (int nt = 0; nt < 16; nt++) { acc[s][nt][0] = 0u; acc[s][nt][1] = 0u; }

        #pragma unroll
        for (int kt = 0; kt < 3; kt++) {
            unsigned a00, a01, a02, a03, a10, a11, a12, a13;
            ldm_x4_trans(a00, a01, a02, a03, a_b0 + kt * (16 * AT_STR * 2));
            ldm_x4_trans(a10, a11, a12, a13, a_b1 + kt * (16 * AT_STR * 2));
            #pragma unroll
            for (int ntp = 0; ntp < 8; ntp++) {
                unsigned b0, b1r, b2r, b3;
                ldm_x4(b0, b1r, b2r, b3,
                       b1_base + (uint32_t)(ntp * 16 * W1_STR * 2) + kt * 32);
                mma_f16acc(acc[0][2*ntp    ], a00, a01, a02, a03, b0,  b1r);
                mma_f16acc(acc[0][2*ntp + 1], a00, a01, a02, a03, b2r, b3);
                mma_f16acc(acc[1][2*ntp    ], a10, a11, a12, a13, b0,  b1r);
                mma_f16acc(acc[1][2*ntp + 1], a10, a11, a12, a13, b2r, b3);
            }
        }

        // bias + relu (half2, in place) -> acc becomes GEMM2 A fragments
        {
            const half2* B1p = g_b1h2 + tg;
            const half2  z   = __float2half2_rn(0.f);
            #pragma unroll
            for (int nt = 0; nt < 16; nt++) {
                half2 bb = B1p[4 * nt];
                #pragma unroll
                for (int s = 0; s < 2; s++) {
                    half2 v0 = __hmax2(__hadd2(*(half2*)&acc[s][nt][0], bb), z);
                    half2 v1 = __hmax2(__hadd2(*(half2*)&acc[s][nt][1], bb), z);
                    acc[s][nt][0] = *(unsigned*)&v0;
                    acc[s][nt][1] = *(unsigned*)&v1;
                }
            }
        }

        // ---- GEMM2: [32 x 128] x w2^T[128 x 16], fp32 accum ----
        float acc2[2][2][4];
        #pragma unroll
        for (int s = 0; s < 2; s++)
            #pragma unroll
            for (int nt = 0; nt < 2; nt++) {
                acc2[s][nt][0] = 0.f; acc2[s][nt][1] = 0.f;
                acc2[s][nt][2] = 0.f; acc2[s][nt][3] = 0.f;
            }
        #pragma unroll
        for (int kt = 0; kt < 8; kt++) {
            unsigned b0, b1r, b2r, b3;
            ldm_x4(b0, b1r, b2r, b3, b2_base + kt * 32);
            #pragma unroll
            for (int s = 0; s < 2; s++) {
                unsigned a0 = acc[s][2*kt][0],   a1 = acc[s][2*kt][1];
                unsigned a2 = acc[s][2*kt+1][0], a3 = acc[s][2*kt+1][1];
                mma_f32acc(acc2[s][0], a0, a1, a2, a3, b0,  b1r);
                mma_f32acc(acc2[s][1], a0, a1, a2, a3, b2r, b3);
            }
        }

        // ---- epilogue ----
        const float* nrow = noise + (((b << 8) + h) << 8);
        const int out_base = ((b*TC) << 16) + (h << 8);

        #pragma unroll
        for (int s = 0; s < 2; s++) {
            const int pix0 = m0 + 16*s + g;
            const int pix1 = pix0 + 8;
            const float mk0 = (nrow[pix0] < 0.5f) ? 1.f : 0.f;
            const float mk1 = (nrow[pix1] < 0.5f) ? 1.f : 0.f;
            #pragma unroll
            for (int nt = 0; nt < 2; nt++) {
                #pragma unroll
                for (int rr = 0; rr < 2; rr++) {
                    int   c   = (nt << 3) + 2*tg + rr;
                    float bb  = b2[c];
                    float gc0 = Gs[(c*3 + 1)*GS_STR + pix0 + 4];
                    float gc1 = Gs[(c*3 + 1)*GS_STR + pix1 + 4];
                    float u0  = (acc2[s][nt][rr]     + bb) * mk0;
                    float u1  = (acc2[s][nt][2 + rr] + bb) * mk1;
                    out[out_base + (c << 16) + pix0] = fminf(fmaxf(gc0 + u0, -2.f), 2.f);
                    out[out_base + (c << 16) + pix1] = fminf(fmaxf(gc1 + u1, -2.f), 2.f);
                }
            }
        }
        __syncthreads();
    }
}

extern "C" void kernel_launch(void* const* d_in, const int* in_sizes, int n_in,
                              void* d_out, int out_size)
{
    const float* grid  = (const float*)d_in[0];
    const float* noise = (const float*)d_in[1];
    const float* w1    = (const float*)d_in[2];
    const float* b1    = (const float*)d_in[3];
    const float* w2    = (const float*)d_in[4];
    const float* b2    = (const float*)d_in[5];
    float* out = (float*)d_out;

    static bool attr_set = false;
    if (!attr_set) {
        cudaFuncSetAttribute(nca_step_kernel,
                             cudaFuncAttributeMaxDynamicSharedMemorySize, SMEM_BYTES);
        attr_set = true;
    }

    int nsm = 148;
    cudaDeviceGetAttribute(&nsm, cudaDevAttrMultiProcessorCount, 0);
    int ncta = nsm * 2;
    if (ncta > NROWT) ncta = NROWT;

    convert_weights_kernel<<<1, THREADS>>>(w1, b1, w2);
    nca_step_kernel<<<ncta, THREADS, SMEM_BYTES>>>(grid, noise, b2, out, ncta);
}

// round 9
// speedup vs baseline: 2.6807x; 1.0021x over previous
#include <cuda_runtime.h>
#include <cuda_fp16.h>
#include <cstdint>

#define TC      16
#define HID     128
#define PCH     48
#define THREADS 256
#define NROWT   8192                // row-tiles: 32 batches * 256 rows

#define GS_STR  264                 // floats per Gs row, interior at col 4 (pix 0..255)
#define AT_STR  264                 // halfs per AsT row
#define W1_STR  56
#define W2_STR  136

// smem: Gs float[16*3*264] | AsT half[48*264] | Wh1 half[128*56] | Wh2 half[16*136]
#define OFF_GS   0
#define OFF_AST  (16*3*GS_STR*4)                  // 50688
#define OFF_WH1  (OFF_AST + PCH*AT_STR*2)         // 76032
#define OFF_WH2  (OFF_WH1 + HID*W1_STR*2)         // 90368
#define SMEM_BYTES (OFF_WH2 + TC*W2_STR*2)        // 94720

// Pre-converted, pre-padded weights (k-permuted w1: k = 16*filter + channel).
__device__ __align__(16) half  g_wh1p[HID * W1_STR];
__device__ __align__(16) half  g_wh2p[TC * W2_STR];
__device__ __align__(16) half2 g_b1h2[HID / 2];

__global__ void convert_weights_kernel(const float* __restrict__ w1,
                                       const float* __restrict__ b1,
                                       const float* __restrict__ w2)
{
    int t = threadIdx.x;
    for (int i = t; i < HID * W1_STR; i += THREADS) g_wh1p[i] = __float2half(0.f);
    for (int i = t; i < TC * W2_STR; i += THREADS) g_wh2p[i] = __float2half(0.f);
    __syncthreads();
    for (int i = t; i < HID * PCH; i += THREADS) {
        int o = i / PCH, p = i % PCH;
        int c = p / 3, f = p % 3;                  // src col p = 3c+f
        g_wh1p[o * W1_STR + f * 16 + c] = __float2half(w1[i]);
    }
    for (int i = t; i < TC * HID; i += THREADS)
        g_wh2p[(i / HID) * W2_STR + (i % HID)] = __float2half(w2[i]);
    if (t < HID / 2)
        g_b1h2[t] = __floats2half2_rn(b1[2 * t], b1[2 * t + 1]);
}

__device__ __forceinline__ void mma_f16acc(unsigned* d,
    unsigned a0, unsigned a1, unsigned a2, unsigned a3,
    unsigned b0, unsigned b1)
{
    asm volatile(
        "mma.sync.aligned.m16n8k16.row.col.f16.f16.f16.f16 "
        "{%0,%1}, {%2,%3,%4,%5}, {%6,%7}, {%0,%1};\n"
        : "+r"(d[0]), "+r"(d[1])
        : "r"(a0), "r"(a1), "r"(a2), "r"(a3), "r"(b0), "r"(b1));
}

__device__ __forceinline__ void mma_f32acc(float* d,
    unsigned a0, unsigned a1, unsigned a2, unsigned a3,
    unsigned b0, unsigned b1)
{
    asm volatile(
        "mma.sync.aligned.m16n8k16.row.col.f32.f16.f16.f32 "
        "{%0,%1,%2,%3}, {%4,%5,%6,%7}, {%8,%9}, {%0,%1,%2,%3};\n"
        : "+f"(d[0]), "+f"(d[1]), "+f"(d[2]), "+f"(d[3])
        : "r"(a0), "r"(a1), "r"(a2), "r"(a3), "r"(b0), "r"(b1));
}

__device__ __forceinline__ void ldm_x4(unsigned& r0, unsigned& r1,
                                       unsigned& r2, unsigned& r3, uint32_t addr)
{
    asm volatile(
        "ldmatrix.sync.aligned.m8n8.x4.shared.b16 {%0,%1,%2,%3}, [%4];\n"
        : "=r"(r0), "=r"(r1), "=r"(r2), "=r"(r3) : "r"(addr));
}

__device__ __forceinline__ void ldm_x4_trans(unsigned& r0, unsigned& r1,
                                             unsigned& r2, unsigned& r3, uint32_t addr)
{
    asm volatile(
        "ldmatrix.sync.aligned.m8n8.x4.trans.shared.b16 {%0,%1,%2,%3}, [%4];\n"
        : "=r"(r0), "=r"(r1), "=r"(r2), "=r"(r3) : "r"(addr));
}

__global__ __launch_bounds__(THREADS, 2)
void nca_step_kernel(const float* __restrict__ grid,
                     const float* __restrict__ noise,
                     const float* __restrict__ b2,
                     float* __restrict__ out,
                     int ncta)
{
    extern __shared__ __align__(128) char smem_raw[];
    float* Gs  = (float*)(smem_raw + OFF_GS);      // [16][3][264], interior at col 4
    half*  AsT = (half*)(smem_raw + OFF_AST);      // [48][264] k-major
    half*  Wh1 = (half*)(smem_raw + OFF_WH1);      // [128][56]
    half*  Wh2 = (half*)(smem_raw + OFF_WH2);      // [16][136]

    const int tid = threadIdx.x;
    const int cta = blockIdx.x;
    const int niter = (NROWT - cta + ncta - 1) / ncta;

    // ---- stage weights once per CTA (vector memcpy of pre-padded layouts) ----
    {
        const uint4* s1 = (const uint4*)g_wh1p;
        uint4*       d1 = (uint4*)Wh1;
        for (int i = tid; i < (HID*W1_STR)/8; i += THREADS) d1[i] = s1[i];
        const uint4* s2 = (const uint4*)g_wh2p;
        uint4*       d2 = (uint4*)Wh2;
        for (int i = tid; i < (TC*W2_STR)/8; i += THREADS) d2[i] = s2[i];
    }

    // ---- per-thread constants ----
    const int lane = tid & 31;
    const int g    = lane >> 2;
    const int tg   = lane & 3;
    const int m0   = (tid >> 5) << 5;              // 32 pixels per warp

    // A (trans) ldmatrix bases for the two 16-px sub-tiles
    const uint32_t ast_sm = (uint32_t)__cvta_generic_to_shared(AsT);
    const uint32_t a_row  = (lane & 7) + ((lane >> 4) << 3);
    const uint32_t a_b0   = ast_sm + (uint32_t)((a_row * AT_STR + m0      + (lane & 8)) * 2);
    const uint32_t a_b1   = ast_sm + (uint32_t)((a_row * AT_STR + m0 + 16 + (lane & 8)) * 2);
    // B ldmatrix bases (n-major 8x8 tile pairs, then k)
    const uint32_t brow = (lane & 7) + ((lane >> 4) << 3);
    const uint32_t bkof = (lane & 8);
    const uint32_t b1_base = (uint32_t)__cvta_generic_to_shared(Wh1) + (brow * W1_STR + bkof) * 2;
    const uint32_t b2_base = (uint32_t)__cvta_generic_to_shared(Wh2) + (brow * W2_STR + bkof) * 2;

    __syncthreads();

    for (int i = 0; i < niter; i++) {
        const int tile = cta + i * ncta;           // row-tile: b*256 + h
        const int b    = tile >> 8;
        const int h    = tile & 255;

        // ---- stage grid row-tile: 48 rows x 64 float4 interior ----
        #pragma unroll
        for (int j = 0; j < 12; j++) {
            int idx   = j * THREADS + tid;       // 0..3071
            int rowid = idx >> 6;                // 0..47
            int c     = rowid / 3;
            int r     = rowid - c * 3;
            int colq  = idx & 63;
            int hh    = h + r - 1;
            float4 v  = make_float4(0.f, 0.f, 0.f, 0.f);
            if ((unsigned)hh < 256u)
                v = *(const float4*)&grid[((((b*TC + c) << 8) + hh) << 8) + (colq << 2)];
            *(float4*)&Gs[(c*3 + r)*GS_STR + 4 + (colq << 2)] = v;
        }
        // halo: 48 rows x 2 side columns (Gs cols 3 and 260) — both OOB -> 0
        if (tid < 96) {
            int rowid = tid >> 1;
            int side  = tid & 1;
            int c     = rowid / 3;
            int r     = rowid - c * 3;
            Gs[(c*3 + r)*GS_STR + (side ? 260 : 3)] = 0.f;
        }
        __syncthreads();

        // ---- perception: 4 px x 1 ch per thread, vector loads + edge shuffles ----
        #pragma unroll
        for (int it = 0; it < 4; it++) {
            int idx  = it * THREADS + tid;       // 0..1023
            int c    = idx >> 6;                 // channel 0..15
            int grp  = idx & 63;                 // = (warp&1)*32 + lane  (lanes consecutive)
            int pix0 = grp << 2;

            float t_[6], mr_[6], bt[6];
            #pragma unroll
            for (int r = 0; r < 3; r++) {
                const int R = c * 3 + r;
                float4 v = *(const float4*)&Gs[R * GS_STR + 4 + pix0];
                float lft = __shfl_up_sync(0xffffffffu, v.w, 1);
                float rgt = __shfl_down_sync(0xffffffffu, v.x, 1);
                if (lane == 0)  lft = Gs[R * GS_STR + 3 + pix0];
                if (lane == 31) rgt = Gs[R * GS_STR + 8 + pix0];
                float* a = (r == 0) ? t_ : (r == 1) ? mr_ : bt;
                a[0] = lft; a[1] = v.x; a[2] = v.y; a[3] = v.z; a[4] = v.w; a[5] = rgt;
            }

            float idv[4], sxv[4], syv[4];
            #pragma unroll
            for (int j = 0; j < 4; j++) {
                float tl = t_[j],  tc_ = t_[j+1],  tr = t_[j+2];
                float ml = mr_[j], mc  = mr_[j+1], mrr = mr_[j+2];
                float bl = bt[j],  bc  = bt[j+1],  br = bt[j+2];
                idv[j] = mc;
                // sobel_x exactly as in reference: [[1,0,1],[2,0,-2],[1,0,-1]]/8
                sxv[j] = (tl + tr + 2.f*ml - 2.f*mrr + bl - br) * 0.125f;
                syv[j] = (tl + 2.f*tc_ + tr - bl - 2.f*bc - br) * 0.125f;
            }

            // pack 4 halfs -> STS.64 per filter row
            half2 p0, p1;
            p0 = __floats2half2_rn(idv[0], idv[1]); p1 = __floats2half2_rn(idv[2], idv[3]);
            *(uint2*)&AsT[c * AT_STR + pix0]        = make_uint2(*(unsigned*)&p0, *(unsigned*)&p1);
            p0 = __floats2half2_rn(sxv[0], sxv[1]); p1 = __floats2half2_rn(sxv[2], sxv[3]);
            *(uint2*)&AsT[(16 + c) * AT_STR + pix0] = make_uint2(*(unsigned*)&p0, *(unsigned*)&p1);
            p0 = __floats2half2_rn(syv[0], syv[1]); p1 = __floats2half2_rn(syv[2], syv[3]);
            *(uint2*)&AsT[(32 + c) * AT_STR + pix0] = make_uint2(*(unsigned*)&p0, *(unsigned*)&p1);
        }
        __syncthreads();

        // ---- GEMM1: [256 x 48] x w1^T[48 x 128], fp16 accum, 2 sub-tiles/warp ----
        unsigned acc[2][16][2];
        #pragma unroll
        for (int s = 0; s < 2; s++)
            #pragma unroll
            for (int nt = 0; nt < 16; nt++) { acc[s][nt][0] = 0u; acc[s][nt][1] = 0u; }

        #pragma unroll
        for (int kt = 0; kt < 3; kt++) {
            unsigned a00, a01, a02, a03, a10, a11, a12, a13;
            ldm_x4_trans(a00, a01, a02, a03, a_b0 + kt * (16 * AT_STR * 2));
            ldm_x4_trans(a10, a11, a12, a13, a_b1 + kt * (16 * AT_STR * 2));
            #pragma unroll
            for (int ntp = 0; ntp < 8; ntp++) {
                unsigned b0, b1r, b2r, b3;
                ldm_x4(b0, b1r, b2r, b3,
                       b1_base + (uint32_t)(ntp * 16 * W1_STR * 2) + kt * 32);
                mma_f16acc(acc[0][2*ntp    ], a00, a01, a02, a03, b0,  b1r);
                mma_f16acc(acc[0][2*ntp + 1], a00, a01, a02, a03, b2r, b3);
                mma_f16acc(acc[1][2*ntp    ], a10, a11, a12, a13, b0,  b1r);
                mma_f16acc(acc[1][2*ntp + 1], a10, a11, a12, a13, b2r, b3);
            }
        }

        // bias + relu (half2, in place) -> acc becomes GEMM2 A fragments
        {
            const half2* B1p = g_b1h2 + tg;
            const half2  z   = __float2half2_rn(0.f);
            #pragma unroll
            for (int nt = 0; nt < 16; nt++) {
                half2 bb = B1p[4 * nt];
                #pragma unroll
                for (int s = 0; s < 2; s++) {
                    half2 v0 = __hmax2(__hadd2(*(half2*)&acc[s][nt][0], bb), z);
                    half2 v1 = __hmax2(__hadd2(*(half2*)&acc[s][nt][1], bb), z);
                    acc[s][nt][0] = *(unsigned*)&v0;
                    acc[s][nt][1] = *(unsigned*)&v1;
                }
            }
        }

        // ---- GEMM2: [32 x 128] x w2^T[128 x 16], fp32 accum ----
        float acc2[2][2][4];
        #pragma unroll
        for (int s = 0; s < 2; s++)
            #pragma unroll
            for (int nt = 0; nt < 2; nt++) {
                acc2[s][nt][0] = 0.f; acc2[s][nt][1] = 0.f;
                acc2[s][nt][2] = 0.f; acc2[s][nt][3] = 0.f;
            }
        #pragma unroll
        for (int kt = 0; kt < 8; kt++) {
            unsigned b0, b1r, b2r, b3;
            ldm_x4(b0, b1r, b2r, b3, b2_base + kt * 32);
            #pragma unroll
            for (int s = 0; s < 2; s++) {
                unsigned a0 = acc[s][2*kt][0],   a1 = acc[s][2*kt][1];
                unsigned a2 = acc[s][2*kt+1][0], a3 = acc[s][2*kt+1][1];
                mma_f32acc(acc2[s][0], a0, a1, a2, a3, b0,  b1r);
                mma_f32acc(acc2[s][1], a0, a1, a2, a3, b2r, b3);
            }
        }

        // ---- epilogue ----
        const float* nrow = noise + (((b << 8) + h) << 8);
        const int out_base = ((b*TC) << 16) + (h << 8);

        #pragma unroll
        for (int s = 0; s < 2; s++) {
            const int pix0 = m0 + 16*s + g;
            const int pix1 = pix0 + 8;
            const float mk0 = (nrow[pix0] < 0.5f) ? 1.f : 0.f;
            const float mk1 = (nrow[pix1] < 0.5f) ? 1.f : 0.f;
            #pragma unroll
            for (int nt = 0; nt < 2; nt++) {
                #pragma unroll
                for (int rr = 0; rr < 2; rr++) {
                    int   c   = (nt << 3) + 2*tg + rr;
                    float bb  = b2[c];
                    float gc0 = Gs[(c*3 + 1)*GS_STR + pix0 + 4];
                    float gc1 = Gs[(c*3 + 1)*GS_STR + pix1 + 4];
                    float u0  = (acc2[s][nt][rr]     + bb) * mk0;
                    float u1  = (acc2[s][nt][2 + rr] + bb) * mk1;
                    out[out_base + (c << 16) + pix0] = fminf(fmaxf(gc0 + u0, -2.f), 2.f);
                    out[out_base + (c << 16) + pix1] = fminf(fmaxf(gc1 + u1, -2.f), 2.f);
                }
            }
        }
        __syncthreads();
    }
}

extern "C" void kernel_launch(void* const* d_in, const int* in_sizes, int n_in,
                              void* d_out, int out_size)
{
    const float* grid  = (const float*)d_in[0];
    const float* noise = (const float*)d_in[1];
    const float* w1    = (const float*)d_in[2];
    const float* b1    = (const float*)d_in[3];
    const float* w2    = (const float*)d_in[4];
    const float* b2    = (const float*)d_in[5];
    float* out = (float*)d_out;

    static bool attr_set = false;
    if (!attr_set) {
        cudaFuncSetAttribute(nca_step_kernel,
                             cudaFuncAttributeMaxDynamicSharedMemorySize, SMEM_BYTES);
        attr_set = true;
    }

    int nsm = 148;
    cudaDeviceGetAttribute(&nsm, cudaDevAttrMultiProcessorCount, 0);
    int ncta = nsm * 2;
    if (ncta > NROWT) ncta = NROWT;

    convert_weights_kernel<<<1, THREADS>>>(w1, b1, w2);
    nca_step_kernel<<<ncta, THREADS, SMEM_BYTES>>>(grid, noise, b2, out, ncta);
}